// round 3
// baseline (speedup 1.0000x reference)
#include <cuda_runtime.h>
#include <math.h>

#define D       2048
#define NROWS   65536
#define NDREAMS 4
#define KMEM    8
#define MCAND   12

#define SIMS_BLOCKS 1024
#define MV_BLOCKS_PER_MAT 64     // Wq / Wg1: 64 blocks x 64 rows
#define WC_BLOCKS 512            // Wc: 512 blocks x 8 warps = 4096 half-rows
#define WM_BLOCKS 256            // Wm: 256 blocks x 8 rows

// ---------------- scratch (zero-initialized at module load) ----------------
__device__ float g_scores[NROWS];
__device__ float g_qv_pre[D];    // zeroed by k6 at end of every launch
__device__ float g_gate_pre[D];  // zeroed by k6
__device__ float g_spre[D];      // zeroed by k6 (after consumption)
__device__ float g_qws[D];
__device__ float g_v[D];         // zeroed by k2 (runs before k3 every launch)
__device__ float g_sraw[D];
__device__ float g_C[MCAND * D];
__device__ int   g_idx[KMEM];
__device__ float g_scalars[2];   // [0]=gate g, [1]=logit bias cb

__device__ __forceinline__ float warp_sum(float v) {
#pragma unroll
    for (int off = 16; off; off >>= 1) v += __shfl_down_sync(0xFFFFFFFFu, v, off);
    return v;
}

// ======================= K1: fused big kernel =======================
// blocks [0, 1024)        : cosine scores (2 rows per warp, z in smem)
// blocks [1024, 1152)     : Wq / Wg1 matvec partials (atomicAdd into pre-zeroed)
// blocks [1152, 1156)     : dreams -> g_C rows 8..11
__global__ __launch_bounds__(256) void k1_fused(const float* __restrict__ z,
                                                const float* __restrict__ h,
                                                const float* __restrict__ mem,
                                                const float* __restrict__ Wq,
                                                const float* __restrict__ Wg1,
                                                const float* __restrict__ noise) {
    __shared__ float zsh[D];
    int b = blockIdx.x, t = threadIdx.x;
    int warp = t >> 5, lane = t & 31;

    if (b < SIMS_BLOCKS) {
#pragma unroll
        for (int k = 0; k < 8; ++k) zsh[t + 256 * k] = z[t + 256 * k];
        __syncthreads();
        const float4* z4 = (const float4*)zsh;
        int wg = b * 8 + warp;                       // 0..8191
#pragma unroll 1
        for (int p = 0; p < 4; ++p) {
            int rA = 2 * wg + 16384 * p;
            const float4* A4 = (const float4*)(mem + (size_t)rA * D);
            const float4* B4 = (const float4*)(mem + (size_t)(rA + 1) * D);
            float da0 = 0, da1 = 0, da2 = 0, da3 = 0;
            float na0 = 0, na1 = 0, na2 = 0, na3 = 0;
            float db0 = 0, db1 = 0, db2 = 0, db3 = 0;
            float nb0 = 0, nb1 = 0, nb2 = 0, nb3 = 0;
#pragma unroll
            for (int it = 0; it < 16; ++it) {
                float4 va = A4[lane + 32 * it];
                float4 vb = B4[lane + 32 * it];
                float4 zz = z4[lane + 32 * it];
                da0 += va.x * zz.x; da1 += va.y * zz.y; da2 += va.z * zz.z; da3 += va.w * zz.w;
                na0 += va.x * va.x; na1 += va.y * va.y; na2 += va.z * va.z; na3 += va.w * va.w;
                db0 += vb.x * zz.x; db1 += vb.y * zz.y; db2 += vb.z * zz.z; db3 += vb.w * zz.w;
                nb0 += vb.x * vb.x; nb1 += vb.y * vb.y; nb2 += vb.z * vb.z; nb3 += vb.w * vb.w;
            }
            float dA = warp_sum((da0 + da1) + (da2 + da3));
            float nA = warp_sum((na0 + na1) + (na2 + na3));
            float dB = warp_sum((db0 + db1) + (db2 + db3));
            float nB = warp_sum((nb0 + nb1) + (nb2 + nb3));
            if (lane == 0) {
                g_scores[rA]     = dA * rsqrtf(nA);
                g_scores[rA + 1] = dB * rsqrtf(nB);
            }
        }
    } else if (b < SIMS_BLOCKS + 2 * MV_BLOCKS_PER_MAT) {
        int mb = b - SIMS_BLOCKS;                        // 0..127
        const float* W   = (mb < MV_BLOCKS_PER_MAT) ? Wq : Wg1;
        float*       dst = (mb < MV_BLOCKS_PER_MAT) ? g_qv_pre : g_gate_pre;
        int rb = (mb & (MV_BLOCKS_PER_MAT - 1)) * 64;
        float acc[8];
#pragma unroll
        for (int k = 0; k < 8; ++k) acc[k] = 0.f;
        for (int i = 0; i < 64; ++i) {
            int row = rb + i;
            float x = (row < D) ? z[row] : h[row - D];
            const float* wr = W + (size_t)row * D;
#pragma unroll
            for (int k = 0; k < 8; ++k) acc[k] += x * wr[t + 256 * k];
        }
#pragma unroll
        for (int k = 0; k < 8; ++k) atomicAdd(&dst[t + 256 * k], acc[k]);
    } else {
        __shared__ float red[8];
        int dm = b - SIMS_BLOCKS - 2 * MV_BLOCKS_PER_MAT;   // 0..3
        float ss = 0.f;
#pragma unroll
        for (int k = 0; k < 8; ++k) {
            int j = t + 256 * k;
            float v = 0.7f * noise[dm * D + j] + 0.3f * z[j];
            zsh[j] = v;
            ss += v * v;
        }
        ss = warp_sum(ss);
        if (lane == 0) red[warp] = ss;
        __syncthreads();
        if (t == 0) {
            float s = 0.f;
#pragma unroll
            for (int w = 0; w < 8; ++w) s += red[w];
            red[0] = s;
        }
        __syncthreads();
        float inv = 1.0f / fmaxf(sqrtf(red[0]), 1e-12f);
#pragma unroll
        for (int k = 0; k < 8; ++k) {
            int j = t + 256 * k;
            g_C[(KMEM + dm) * D + j] = zsh[j] * inv;
        }
    }
}

// ======================= K2: single-pass top-8 + activations ==================
__global__ __launch_bounds__(1024) void k2_select(const float* __restrict__ bq,
                                                  const float* __restrict__ ws,
                                                  const float* __restrict__ bs,
                                                  const float* __restrict__ bc,
                                                  const float* __restrict__ bg1,
                                                  const float* __restrict__ wg2,
                                                  const float* __restrict__ bg2) {
    __shared__ float pv[32 * KMEM];   // warp top-8 pool (values)
    __shared__ int   pi[32 * KMEM];   // warp top-8 pool (bank indices)
    __shared__ float scb[32], sgp[32];
    int t = threadIdx.x, lane = t & 31, warp = t >> 5;

    // --- phase 1: per-thread top-8 (sorted descending) over 64 strided values ---
    float bv[KMEM];
    int   bi[KMEM];
#pragma unroll
    for (int q = 0; q < KMEM; ++q) { bv[q] = -INFINITY; bi[q] = 0; }
    const float4* sc4 = (const float4*)g_scores;
#pragma unroll 1
    for (int f = 0; f < 16; ++f) {
        int fi = t + 1024 * f;
        float4 v = sc4[fi];
        int base = fi * 4;
        float vals[4] = {v.x, v.y, v.z, v.w};
#pragma unroll
        for (int c = 0; c < 4; ++c) {
            float s = vals[c];
            if (s > bv[KMEM - 1]) {
                // place at bottom, bubble up (list stays sorted descending)
                bv[KMEM - 1] = s; bi[KMEM - 1] = base + c;
#pragma unroll
                for (int q = KMEM - 1; q > 0; --q) {
                    if (bv[q] > bv[q - 1]) {
                        float tv = bv[q - 1]; int ti = bi[q - 1];
                        bv[q - 1] = bv[q]; bi[q - 1] = bi[q];
                        bv[q] = tv; bi[q] = ti;
                    }
                }
            }
        }
    }

    // --- phase 2: warp merge (32 sorted 8-lists -> warp top-8) ---
#pragma unroll 1
    for (int p = 0; p < KMEM; ++p) {
        float v = bv[0]; int id = bi[0]; int ln = lane;
#pragma unroll
        for (int off = 16; off; off >>= 1) {
            float ov = __shfl_down_sync(0xFFFFFFFFu, v, off);
            int oid  = __shfl_down_sync(0xFFFFFFFFu, id, off);
            int oln  = __shfl_down_sync(0xFFFFFFFFu, ln, off);
            if (ov > v) { v = ov; id = oid; ln = oln; }
        }
        int wln = __shfl_sync(0xFFFFFFFFu, ln, 0);
        if (lane == 0) { pv[warp * KMEM + p] = v; pi[warp * KMEM + p] = id; }
        if (lane == wln) {
#pragma unroll
            for (int q = 0; q < KMEM - 1; ++q) { bv[q] = bv[q + 1]; bi[q] = bi[q + 1]; }
            bv[KMEM - 1] = -INFINITY;
        }
    }
    __syncthreads();

    // --- phase 3: warp 0 selects global top-8 from the 256-entry pool ---
    if (warp == 0) {
#pragma unroll 1
        for (int p = 0; p < KMEM; ++p) {
            float best = -INFINITY; int bslot = lane;
#pragma unroll
            for (int e = 0; e < 8; ++e) {
                int slot = lane + 32 * e;
                float v = pv[slot];
                if (v > best) { best = v; bslot = slot; }
            }
#pragma unroll
            for (int off = 16; off; off >>= 1) {
                float ov = __shfl_down_sync(0xFFFFFFFFu, best, off);
                int osl  = __shfl_down_sync(0xFFFFFFFFu, bslot, off);
                if (ov > best) { best = ov; bslot = osl; }
            }
            if (lane == 0) {
                g_idx[p] = pi[bslot];
                pv[bslot] = -INFINITY;
            }
            __syncwarp();
        }
    }

    // --- phase 4: activations, scalars, zero g_v ---
    for (int j = t; j < D; j += 1024) {
        float qv = tanhf(g_qv_pre[j] + bq[j]);
        g_qws[j] = qv * ws[j];
        g_v[j] = 0.f;
    }
    __syncthreads();
    float cbp = 0.f, gp = 0.f;
    for (int j = t; j < D; j += 1024) {
        cbp += bc[j] * g_qws[j];
        float hg = tanhf(g_gate_pre[j] + bg1[j]);
        gp += hg * wg2[j];
    }
    cbp = warp_sum(cbp);
    gp  = warp_sum(gp);
    if (lane == 0) { scb[warp] = cbp; sgp[warp] = gp; }
    __syncthreads();
    if (t == 0) {
        float c = 0.f, g = 0.f;
#pragma unroll
        for (int w = 0; w < 32; ++w) { c += scb[w]; g += sgp[w]; }
        g_scalars[1] = c + bs[0];
        g_scalars[0] = 1.0f / (1.0f + expf(-(g + bg2[0])));
    }
}

// ======================= K3: v = Wc @ qws (split) + gather protos =============
__global__ __launch_bounds__(256) void k3_v_gather(const float* __restrict__ mem,
                                                   const float* __restrict__ Wc) {
    int b = blockIdx.x;
    if (b < KMEM) {
        int r = g_idx[b];
        const float4* src = (const float4*)(mem + (size_t)r * D);
        float4* dst = (float4*)(g_C + b * D);
        for (int j = threadIdx.x; j < D / 4; j += 256) dst[j] = src[j];
    } else {
        int warp = threadIdx.x >> 5, lane = threadIdx.x & 31;
        int w = (b - KMEM) * 8 + warp;           // 0..4095
        int row = w >> 1, half = w & 1;
        const float4* wr = (const float4*)(Wc + (size_t)row * D + half * (D / 2));
        const float4* q4 = (const float4*)(g_qws + half * (D / 2));
        float a0 = 0, a1 = 0, a2 = 0, a3 = 0;
#pragma unroll
        for (int it = 0; it < 8; ++it) {
            float4 wv = wr[lane + 32 * it];
            float4 qv = q4[lane + 32 * it];
            a0 += wv.x * qv.x; a1 += wv.y * qv.y; a2 += wv.z * qv.z; a3 += wv.w * qv.w;
        }
        float s = warp_sum((a0 + a1) + (a2 + a3));
        if (lane == 0) atomicAdd(&g_v[row], s);
    }
}

// ======================= K4: logits -> softmax -> s_raw =======================
__global__ __launch_bounds__(1024) void k4_attn() {
    __shared__ float wred[32][MCAND];
    __shared__ float attn[MCAND];
    int t = threadIdx.x, lane = t & 31, warp = t >> 5;

    float part[MCAND];
#pragma unroll
    for (int m = 0; m < MCAND; ++m) part[m] = 0.f;
    for (int j = t; j < D; j += 1024) {
        float vj = g_v[j];
#pragma unroll
        for (int m = 0; m < MCAND; ++m) part[m] += g_C[m * D + j] * vj;
    }
#pragma unroll
    for (int m = 0; m < MCAND; ++m) part[m] = warp_sum(part[m]);
    if (lane == 0) {
#pragma unroll
        for (int m = 0; m < MCAND; ++m) wred[warp][m] = part[m];
    }
    __syncthreads();
    if (t == 0) {
        float lg[MCAND]; float mx = -INFINITY;
#pragma unroll
        for (int m = 0; m < MCAND; ++m) {
            float s = g_scalars[1];
            for (int w = 0; w < 32; ++w) s += wred[w][m];
            lg[m] = s;
            mx = fmaxf(mx, s);
        }
        float den = 0.f;
#pragma unroll
        for (int m = 0; m < MCAND; ++m) { lg[m] = expf(lg[m] - mx); den += lg[m]; }
#pragma unroll
        for (int m = 0; m < MCAND; ++m) attn[m] = lg[m] / den;
    }
    __syncthreads();
    for (int j = t; j < D; j += 1024) {
        float s = 0.f;
#pragma unroll
        for (int m = 0; m < MCAND; ++m) s += attn[m] * g_C[m * D + j];
        g_sraw[j] = s;
    }
}

// ======================= K5: s_pre = s_raw @ Wm (split-K atomic) ==============
__global__ __launch_bounds__(256) void k5_wm(const float* __restrict__ Wm) {
    int b = blockIdx.x, t = threadIdx.x;
    int rb = b * 8;                              // 256 blocks x 8 rows
    float acc[8];
#pragma unroll
    for (int k = 0; k < 8; ++k) acc[k] = 0.f;
#pragma unroll
    for (int i = 0; i < 8; ++i) {
        float x = g_sraw[rb + i];
        const float* wr = Wm + (size_t)(rb + i) * D;
#pragma unroll
        for (int k = 0; k < 8; ++k) acc[k] += x * wr[t + 256 * k];
    }
#pragma unroll
    for (int k = 0; k < 8; ++k) atomicAdd(&g_spre[t + 256 * k], acc[k]);
}

// ======================= K6: output + reset accumulators for next replay ======
__global__ __launch_bounds__(256) void k6_out(const float* __restrict__ bm,
                                              float* __restrict__ out) {
    int j = blockIdx.x * 256 + threadIdx.x;
    out[j] = g_scalars[0] * tanhf(g_spre[j] + bm[j]);
    g_spre[j] = 0.f;
    g_qv_pre[j] = 0.f;
    g_gate_pre[j] = 0.f;
}

// ======================= launch =======================
extern "C" void kernel_launch(void* const* d_in, const int* in_sizes, int n_in,
                              void* d_out, int out_size) {
    const float* z     = (const float*)d_in[0];
    const float* h     = (const float*)d_in[1];
    const float* mem   = (const float*)d_in[2];
    const float* noise = (const float*)d_in[3];
    const float* Wq    = (const float*)d_in[4];
    const float* bq    = (const float*)d_in[5];
    const float* Wc    = (const float*)d_in[6];
    const float* bc    = (const float*)d_in[7];
    const float* ws    = (const float*)d_in[8];
    const float* bs    = (const float*)d_in[9];
    const float* Wm    = (const float*)d_in[10];
    const float* bm    = (const float*)d_in[11];
    const float* Wg1   = (const float*)d_in[12];
    const float* bg1   = (const float*)d_in[13];
    const float* wg2   = (const float*)d_in[14];
    const float* bg2   = (const float*)d_in[15];
    float* out = (float*)d_out;

    k1_fused<<<SIMS_BLOCKS + 2 * MV_BLOCKS_PER_MAT + NDREAMS, 256>>>(z, h, mem, Wq, Wg1, noise);
    k2_select<<<1, 1024>>>(bq, ws, bs, bc, bg1, wg2, bg2);
    k3_v_gather<<<KMEM + WC_BLOCKS, 256>>>(mem, Wc);
    k4_attn<<<1, 1024>>>();
    k5_wm<<<WM_BLOCKS, 256>>>(Wm);
    k6_out<<<D / 256, 256>>>(bm, out);
}